// round 13
// baseline (speedup 1.0000x reference)
#include <cuda_runtime.h>
#include <cuda_fp16.h>

#define NN 100000
#define EE 1600000
#define TILES ((NN + 127) / 128)
#define AGG_BLOCKS 592   // persistent aggm grid: 4 blocks/SM * 148, single wave

// ---------------- scratch (static __device__, no allocation) ----------------
// Per tile: 6 fp16 planes: h set0 (k0,k64), h set1 (k0,k64), m (k0,k64).
// Plane = 128 rows x 128B (64 fp16, SW128-swizzled within row) = 16KB.
__device__ uint4 g_A[(size_t)TILES * 6 * 1024];   // ~77 MB
__device__ uint4 g_B[4 * 4 * 1024];               // per layer: 4 chunk planes, fp16
__device__ float g_s[(size_t)NN * 40];            // layer-4 self term, fp32
__device__ unsigned g_t[(size_t)NN * 24];         // layer-4 neigh term, fp16 (40 vals, pad 96B)
__device__ int   g_deg[NN];
__device__ int   g_rp[NN + 1];
__device__ int   g_cur[NN];
__device__ int   g_col[EE];
__device__ int   g_bsum[256];
__device__ int   g_flag[3 * TILES];               // per-layer tile completion counters

// ---------------- helpers ----------------
__device__ __forceinline__ int swz(int x) { return x ^ ((x >> 3) & 0x70); }

__device__ __forceinline__ uint2 pack_h4(float4 v) {
    __half2 a = __floats2half2_rn(v.x, v.y);
    __half2 b = __floats2half2_rn(v.z, v.w);
    uint2 r;
    r.x = *(unsigned*)&a;
    r.y = *(unsigned*)&b;
    return r;
}

__device__ __forceinline__ unsigned smem_u32(const void* p) {
    unsigned a;
    asm("{ .reg .u64 t; cvta.to.shared.u64 t, %1; cvt.u32.u64 %0, t; }" : "=r"(a) : "l"(p));
    return a;
}
__device__ __forceinline__ void cp16(unsigned s, const void* g) {
    asm volatile("cp.async.cg.shared.global [%0], [%1], 16;" :: "r"(s), "l"(g));
}
__device__ __forceinline__ void cp_commit() { asm volatile("cp.async.commit_group;"); }
__device__ __forceinline__ void cp_wait0() { asm volatile("cp.async.wait_group 0;"); }
__device__ __forceinline__ void cp_wait1() { asm volatile("cp.async.wait_group 1;"); }

__device__ __forceinline__ void grid_wait() {
    asm volatile("griddepcontrol.wait;" ::: "memory");
}
__device__ __forceinline__ void grid_trigger() {
    asm volatile("griddepcontrol.launch_dependents;");
}

__device__ __forceinline__ void ldm_x4(unsigned* r, unsigned addr) {
    asm volatile("ldmatrix.sync.aligned.m8n8.x4.shared.b16 {%0,%1,%2,%3}, [%4];"
                 : "=r"(r[0]), "=r"(r[1]), "=r"(r[2]), "=r"(r[3]) : "r"(addr));
}
__device__ __forceinline__ void mma_f16(float* d, const unsigned* a, unsigned b0, unsigned b1) {
    asm volatile(
        "mma.sync.aligned.m16n8k16.row.col.f32.f16.f16.f32 "
        "{%0,%1,%2,%3}, {%4,%5,%6,%7}, {%8,%9}, {%0,%1,%2,%3};"
        : "+f"(d[0]), "+f"(d[1]), "+f"(d[2]), "+f"(d[3])
        : "r"(a[0]), "r"(a[1]), "r"(a[2]), "r"(a[3]), "r"(b0), "r"(b1));
}

__device__ __forceinline__ void mma_chunk(float acc[4][4][4], unsigned Ap, unsigned Bp,
                                          int arow, int brow, int lane) {
#pragma unroll
    for (int ks = 0; ks < 4; ks++) {
        unsigned afr[4][4];
        {
            int seg = ks * 2 + (lane >> 4);
            int inner = swz(((arow & 7) << 7) + seg * 16);
#pragma unroll
            for (int mt = 0; mt < 4; mt++)
                ldm_x4(afr[mt], Ap + (unsigned)((((arow >> 3) + 2 * mt) << 10) + inner));
        }
        unsigned bfr[2][4];
        {
            int seg = ks * 2 + ((lane >> 3) & 1);
            int inner = swz(((brow & 7) << 7) + seg * 16);
#pragma unroll
            for (int nb = 0; nb < 2; nb++)
                ldm_x4(bfr[nb], Bp + (unsigned)((((brow >> 3) + 2 * nb) << 10) + inner));
        }
#pragma unroll
        for (int mt = 0; mt < 4; mt++)
#pragma unroll
            for (int nt = 0; nt < 4; nt++)
                mma_f16(acc[mt][nt], afr[mt],
                        bfr[nt >> 1][(nt & 1) * 2], bfr[nt >> 1][(nt & 1) * 2 + 1]);
    }
}

// ---------------- prep: x -> h set0 planes + all weights + zero flags ----------------
__global__ void k_prep_all(const float* __restrict__ x,
                           const float* __restrict__ ws1, const float* __restrict__ wn1,
                           const float* __restrict__ ws2, const float* __restrict__ wn2,
                           const float* __restrict__ ws3, const float* __restrict__ wn3,
                           const float* __restrict__ ws4, const float* __restrict__ wn4,
                           int n) {
    int bx = blockIdx.x;
    if (bx < 64) {
        int gt = bx * 256 + threadIdx.x;
        if (gt < 3 * TILES) g_flag[gt] = 0;
        int layer = bx >> 4;
        int idx = (bx & 15) * 256 + threadIdx.x;   // 0..4095
        int f = idx >> 5, k = (idx & 31) << 2;
        int kb = (k & 63) << 1;
        int off = ((f >> 3) << 10) + swz(((f & 7) << 7) + kb);
        if (layer < 3) {
            const float* ws = (layer == 0) ? ws1 : (layer == 1) ? ws2 : ws3;
            const float* wn = (layer == 0) ? wn1 : (layer == 1) ? wn2 : wn3;
            float4 vs = *(const float4*)(ws + (size_t)f * 128 + k);
            float4 vn = *(const float4*)(wn + (size_t)f * 128 + k);
            int chunk = k >> 6;
            char* b0 = (char*)g_B + ((size_t)layer * 4 + chunk) * 16384;
            char* b1 = (char*)g_B + ((size_t)layer * 4 + chunk + 2) * 16384;
            *(uint2*)(b0 + off) = pack_h4(vs);
            *(uint2*)(b1 + off) = pack_h4(vn);
        } else {
            float4 v = make_float4(0.f, 0.f, 0.f, 0.f);
            if (f < 40) v = *(const float4*)(ws4 + (size_t)f * 128 + k);
            else if (f < 80) v = *(const float4*)(wn4 + (size_t)(f - 40) * 128 + k);
            int chunk = k >> 6;
            char* b0 = (char*)g_B + ((size_t)3 * 4 + chunk) * 16384;
            *(uint2*)(b0 + off) = pack_h4(v);
        }
        return;
    }
    int idx = (bx - 64) * 256 + threadIdx.x;
    if (idx >= n * 32) return;
    int node = idx >> 5, k = (idx & 31) << 2;
    float4 v = *(const float4*)(x + (size_t)node * 128 + k);
    uint2 q = pack_h4(v);
    int tile = node >> 7, r = node & 127, chunk = k >> 6, kb = (k & 63) << 1;
    char* base = (char*)g_A + ((size_t)tile * 6 + chunk) * 16384;   // h set 0
    int off = ((r >> 3) << 10) + swz(((r & 7) << 7) + kb);
    *(uint2*)(base + off) = q;
}

// ---------------- CSR build (side stream) ----------------
__global__ void k_zero_deg(int n) {
    int i = blockIdx.x * 256 + threadIdx.x;
    if (i < n) g_deg[i] = 0;
}
__global__ void k_count(const int* __restrict__ dst, int e) {
    int i = blockIdx.x * blockDim.x + threadIdx.x;
    if (i < e) atomicAdd(&g_deg[dst[i]], 1);
}
__global__ void k_scan1(int n) {
    __shared__ int s[512];
    int i = blockIdx.x * 512 + threadIdx.x;
    int v = (i < n) ? g_deg[i] : 0;
    s[threadIdx.x] = v;
    __syncthreads();
    for (int off = 1; off < 512; off <<= 1) {
        int t = (threadIdx.x >= off) ? s[threadIdx.x - off] : 0;
        __syncthreads();
        s[threadIdx.x] += t;
        __syncthreads();
    }
    if (i < n) g_rp[i] = s[threadIdx.x] - v;
    if (threadIdx.x == 511) g_bsum[blockIdx.x] = s[511];
}
__global__ void k_scan3b(int n, int e, int nb) {
    __shared__ int s[512];
    int tid = threadIdx.x, bid = blockIdx.x;
    s[tid] = (tid < nb && tid < bid) ? g_bsum[tid] : 0;
    __syncthreads();
    for (int off = 256; off >= 1; off >>= 1) {
        if (tid < off) s[tid] += s[tid + off];
        __syncthreads();
    }
    int offv = s[0];
    int i = bid * 512 + tid;
    if (i < n) {
        int r = g_rp[i] + offv;
        g_rp[i] = r;
        g_cur[i] = r;
    }
    if (i == 0) g_rp[n] = e;
}
__global__ void k_scatter(const int* __restrict__ src, const int* __restrict__ dst, int e) {
    int i = blockIdx.x * blockDim.x + threadIdx.x;
    if (i < e) {
        int d = dst[i];
        int p = atomicAdd(&g_cur[d], 1);
        g_col[p] = src[i];
    }
}

// ---------------- aggregation (persistent): m[v] = mean_in h_set[src] ----------------
__global__ __launch_bounds__(256)
void k_aggm(int n, int* __restrict__ flag, int hset) {
    grid_wait();
    if (threadIdx.x == 0) grid_trigger();
    const int wid = threadIdx.x >> 5;
    const int lane = threadIdx.x & 31;
    const int chunkp = lane >> 4, kb = (lane & 15) << 3;
    const char* Ab = (const char*)g_A;
    const int hs2 = hset * 2;
    const int nchunks = (n + 7) / 8;

    for (int c = blockIdx.x; c < nchunks; c += gridDim.x) {
        int w = c * 8 + wid;
        if (w < n) {
            int beg = g_rp[w], end = g_rp[w + 1];
            float4 acc = make_float4(0.f, 0.f, 0.f, 0.f);
            for (int e = beg; e < end; e += 4) {
                int i1 = min(e + 1, end - 1);
                int i2 = min(e + 2, end - 1);
                int i3 = min(e + 3, end - 1);
                int u0 = g_col[e], u1 = g_col[i1], u2 = g_col[i2], u3 = g_col[i3];
#define ROWADDR(u) (Ab + ((size_t)((u >> 7) * 6 + hs2 + chunkp)) * 16384 + \
                    (((u & 127) >> 3) << 10) + swz((((u & 127) & 7) << 7) + kb))
                uint2 q0 = *(const uint2*)ROWADDR(u0);
                uint2 q1 = *(const uint2*)ROWADDR(u1);
                uint2 q2 = *(const uint2*)ROWADDR(u2);
                uint2 q3 = *(const uint2*)ROWADDR(u3);
#undef ROWADDR
#define ACC4(q) do { \
                float2 f0 = __half22float2(*(__half2*)&(q).x); \
                float2 f1 = __half22float2(*(__half2*)&(q).y); \
                acc.x += f0.x; acc.y += f0.y; acc.z += f1.x; acc.w += f1.y; } while (0)
                ACC4(q0);
                if (e + 1 < end) ACC4(q1);
                if (e + 2 < end) ACC4(q2);
                if (e + 3 < end) ACC4(q3);
#undef ACC4
            }
            float inv = 1.0f / (float)max(end - beg, 1);
            acc.x *= inv; acc.y *= inv; acc.z *= inv; acc.w *= inv;

            int tile = w >> 7, r = w & 127;
            char* base = (char*)g_A + ((size_t)tile * 6 + 4 + chunkp) * 16384;  // m planes
            int off = ((r >> 3) << 10) + swz(((r & 7) << 7) + kb);
            *(uint2*)(base + off) = pack_h4(acc);
        }
        __syncthreads();
        if (threadIdx.x == 0) {
            __threadfence();
            atomicAdd(flag + (c >> 4), 1);
        }
    }
}

// ---------------- GEMM pieces ----------------
// load one 16KB A plane + one 16KB B plane into buffer buf (0/1); one commit group
__device__ __forceinline__ void prefetch2(char* smembase, int buf, const uint4* sa,
                                          const uint4* sb, int tid) {
    char* p = smembase + buf * 32768;
    unsigned da = smem_u32(p);
#pragma unroll
    for (int i = 0; i < 4; i++) cp16(da + (tid + i * 256) * 16, sa + tid + i * 256);
    unsigned db = smem_u32(p + 16384);
#pragma unroll
    for (int i = 0; i < 4; i++) cp16(db + (tid + i * 256) * 16, sb + tid + i * 256);
    cp_commit();
}

// hidden layers: phase 1 = h set hset x Ws; phase 2 (per-tile flag gated) =
// m x Wn. Epilogue writes h set 1-hset (never read by the in-flight aggm).
__global__ __launch_bounds__(256, 2)
void k_gemm_hid(const uint4* __restrict__ Bw, const float* __restrict__ bias,
                const int* __restrict__ flag, int hset, int n) {
    extern __shared__ char smem[];
    const int tid = threadIdx.x, wid = tid >> 5, lane = tid & 31;
    const int mh = wid >> 2, nq = wid & 3;
    const size_t tile = blockIdx.x;
    const unsigned sbase = smem_u32(smem);
    const uint4* gAh = g_A + (tile * 6 + (size_t)hset * 2) * 1024;
    const uint4* gAm = g_A + (tile * 6 + 4) * 1024;

    float acc[4][4][4];
#pragma unroll
    for (int a = 0; a < 4; a++)
#pragma unroll
        for (int b = 0; b < 4; b++)
#pragma unroll
            for (int c = 0; c < 4; c++) acc[a][b][c] = 0.f;

    const int arow = mh * 64 + (lane & 15);
    const int brow = nq * 32 + ((lane >> 4) << 3) + (lane & 7);

    // phase 1: h chunks (safe: aggm's grid_wait => previous gemm complete)
    prefetch2(smem, 0, gAh, Bw, tid);
    prefetch2(smem, 1, gAh + 1024, Bw + 1024, tid);
    cp_wait1();
    __syncthreads();
    mma_chunk(acc, sbase, sbase + 16384u, arow, brow, lane);
    cp_wait0();
    __syncthreads();
    mma_chunk(acc, sbase + 32768u, sbase + 49152u, arow, brow, lane);

    // phase 2: wait for THIS tile's m planes
    if (tid == 0) {
        int cnt = min(16, (n + 7) / 8 - (int)tile * 16);
        while (atomicAdd((int*)(flag + tile), 0) < cnt) __nanosleep(64);
    }
    __syncthreads();
    __threadfence();
    prefetch2(smem, 0, gAm, Bw + 2048, tid);
    prefetch2(smem, 1, gAm + 1024, Bw + 3072, tid);
    cp_wait1();
    __syncthreads();
    mma_chunk(acc, sbase, sbase + 16384u, arow, brow, lane);
    cp_wait0();
    __syncthreads();
    mma_chunk(acc, sbase + 32768u, sbase + 49152u, arow, brow, lane);
    __syncthreads();

    if (tid == 0) grid_trigger();

    // epilogue: write h set 1-hset
    const size_t base = tile * 128;
    const int rr = lane >> 2, cc = (lane & 3) * 2;
    __half* stg = (__half*)smem;   // stride 132 halves
#pragma unroll
    for (int mt = 0; mt < 4; mt++)
#pragma unroll
        for (int nt = 0; nt < 4; nt++) {
            int r = mh * 64 + mt * 16 + rr;
            int col = nq * 32 + nt * 8 + cc;
            float bv0 = __ldg(bias + col), bv1 = __ldg(bias + col + 1);
            float v0 = fmaxf(acc[mt][nt][0] + bv0, 0.f);
            float v1 = fmaxf(acc[mt][nt][1] + bv1, 0.f);
            float v2 = fmaxf(acc[mt][nt][2] + bv0, 0.f);
            float v3 = fmaxf(acc[mt][nt][3] + bv1, 0.f);
            *(__half2*)(stg + r * 132 + col) = __floats2half2_rn(v0, v1);
            *(__half2*)(stg + (r + 8) * 132 + col) = __floats2half2_rn(v2, v3);
        }
    __syncthreads();
    const int ws2 = (1 - hset) * 2;
    for (int t = tid; t < 4096; t += 256) {
        int nn = t >> 5, g = t & 31;
        size_t gn = base + nn;
        if (gn < (size_t)n) {
            uint2 q = *(uint2*)(stg + nn * 132 + g * 4);
            int k0 = g * 4;
            int chunk = k0 >> 6, kb = (k0 & 63) << 1;
            char* bA = (char*)g_A + (tile * 6 + ws2 + chunk) * 16384;
            int off = ((nn >> 3) << 10) + swz(((nn & 7) << 7) + kb);
            *(uint2*)(bA + off) = q;
        }
    }
}

// final layer: st = [Ws4;Wn4] h3 over K=128. Reads h set 1. Entry wait; triggers aggf.
__global__ __launch_bounds__(256, 2)
void k_gemm_fin(const uint4* __restrict__ Bw, const float* __restrict__ bias, int n) {
    grid_wait();
    extern __shared__ char smem[];
    const int tid = threadIdx.x, wid = tid >> 5, lane = tid & 31;
    const int mh = wid >> 2, nq = wid & 3;
    const size_t tile = blockIdx.x;
    const unsigned sbase = smem_u32(smem);
    const uint4* gAt = g_A + (tile * 6 + 2) * 1024;   // h set 1

    float acc[4][4][4];
#pragma unroll
    for (int a = 0; a < 4; a++)
#pragma unroll
        for (int b = 0; b < 4; b++)
#pragma unroll
            for (int c = 0; c < 4; c++) acc[a][b][c] = 0.f;

    const int arow = mh * 64 + (lane & 15);
    const int brow = nq * 32 + ((lane >> 4) << 3) + (lane & 7);

    prefetch2(smem, 0, gAt, Bw, tid);
    prefetch2(smem, 1, gAt + 1024, Bw + 1024, tid);
    cp_wait1();
    __syncthreads();
    mma_chunk(acc, sbase, sbase + 16384u, arow, brow, lane);
    cp_wait0();
    __syncthreads();
    mma_chunk(acc, sbase + 32768u, sbase + 49152u, arow, brow, lane);
    __syncthreads();

    if (tid == 0) grid_trigger();

    const size_t base = tile * 128;
    const int rr = lane >> 2, cc = (lane & 3) * 2;
    float* stage = (float*)smem;   // stride 84 floats, cols 0..79
#pragma unroll
    for (int mt = 0; mt < 4; mt++)
#pragma unroll
        for (int nt = 0; nt < 4; nt++) {
            int col = nq * 32 + nt * 8 + cc;
            if (col < 80) {
                int r = mh * 64 + mt * 16 + rr;
                stage[r * 84 + col] = acc[mt][nt][0];
                stage[r * 84 + col + 1] = acc[mt][nt][1];
                stage[(r + 8) * 84 + col] = acc[mt][nt][2];
                stage[(r + 8) * 84 + col + 1] = acc[mt][nt][3];
            }
        }
    __syncthreads();
    for (int t = tid; t < 128 * 10; t += 256) {
        int nn = t / 10, c4 = t % 10;
        size_t gn = base + nn;
        if (gn < (size_t)n)
            *(float4*)(g_s + gn * 40 + c4 * 4) = *(float4*)(stage + nn * 84 + c4 * 4);
    }
    for (int t = tid; t < 128 * 20; t += 256) {
        int nn = t / 20, j = t % 20;
        size_t gn = base + nn;
        if (gn < (size_t)n) {
            __half2 h = __floats2half2_rn(stage[nn * 84 + 40 + 2 * j],
                                          stage[nn * 84 + 41 + 2 * j]);
            g_t[gn * 24 + j] = *(unsigned*)&h;
        }
    }
}

// ---------------- final aggregation: out[v] = s[v] + mean_t + b (fp16 gather) ----------------
__global__ __launch_bounds__(256)
void k_aggf(const float* __restrict__ b, float* __restrict__ out, int n) {
    grid_wait();
    int w = (blockIdx.x * 256 + threadIdx.x) >> 5;
    int lane = threadIdx.x & 31;
    if (w >= n) return;
    int beg = g_rp[w], end = g_rp[w + 1];

    const int l = min(lane, 19);
    float2 acc = make_float2(0.f, 0.f);
    for (int e = beg; e < end; e += 2) {
        int i1 = min(e + 1, end - 1);
        int u0 = g_col[e], u1 = g_col[i1];
        unsigned q0 = g_t[(size_t)u0 * 24 + l];
        unsigned q1 = g_t[(size_t)u1 * 24 + l];
        if (lane < 20) {
            float2 f0 = __half22float2(*(__half2*)&q0);
            acc.x += f0.x; acc.y += f0.y;
            if (e + 1 < end) {
                float2 f1 = __half22float2(*(__half2*)&q1);
                acc.x += f1.x; acc.y += f1.y;
            }
        }
    }
    if (lane < 20) {
        float inv = 1.0f / (float)max(end - beg, 1);
        float2 s = *(const float2*)(g_s + (size_t)w * 40 + 2 * lane);
        float2 bb = *(const float2*)(b + 2 * lane);
        float2 r;
        r.x = fmaf(acc.x, inv, s.x + bb.x);
        r.y = fmaf(acc.y, inv, s.y + bb.y);
        *(float2*)(out + (size_t)w * 40 + 2 * lane) = r;
    }
}

// ---------------- PDL launch helper ----------------
template <typename K, typename... Args>
static void launch_pdl(K kern, int grid, int block, size_t smem, Args... args) {
    cudaLaunchConfig_t cfg = {};
    cfg.gridDim = dim3(grid, 1, 1);
    cfg.blockDim = dim3(block, 1, 1);
    cfg.dynamicSmemBytes = smem;
    cfg.stream = 0;
    cudaLaunchAttribute attr[1];
    attr[0].id = cudaLaunchAttributeProgrammaticStreamSerialization;
    attr[0].val.programmaticStreamSerializationAllowed = 1;
    cfg.attrs = attr;
    cfg.numAttrs = 1;
    cudaLaunchKernelEx(&cfg, kern, args...);
}

// ---------------- launch ----------------
extern "C" void kernel_launch(void* const* d_in, const int* in_sizes, int n_in,
                              void* d_out, int out_size) {
    const float* x   = (const float*)d_in[0];
    const int*   src = (const int*)d_in[1];
    const int*   dst = (const int*)d_in[2];
    const float* ws1 = (const float*)d_in[3];
    const float* wn1 = (const float*)d_in[4];
    const float* b1  = (const float*)d_in[5];
    const float* ws2 = (const float*)d_in[6];
    const float* wn2 = (const float*)d_in[7];
    const float* b2  = (const float*)d_in[8];
    const float* ws3 = (const float*)d_in[9];
    const float* wn3 = (const float*)d_in[10];
    const float* b3  = (const float*)d_in[11];
    const float* ws4 = (const float*)d_in[12];
    const float* wn4 = (const float*)d_in[13];
    const float* b4  = (const float*)d_in[14];

    const int n = in_sizes[0] / 128;
    const int E = in_sizes[1];
    const int tiles = (n + 127) / 128;

    const int SMEM = 2 * 32768;
    cudaFuncSetAttribute(k_gemm_hid, cudaFuncAttributeMaxDynamicSharedMemorySize, SMEM);
    cudaFuncSetAttribute(k_gemm_fin, cudaFuncAttributeMaxDynamicSharedMemorySize, SMEM);

    uint4* pB;
    int* pF;
    cudaGetSymbolAddress((void**)&pB, g_B);
    cudaGetSymbolAddress((void**)&pF, g_flag);

    // fork: CSR chain on a side stream, overlapped with preps
    cudaStream_t s2;
    cudaStreamCreateWithFlags(&s2, cudaStreamNonBlocking);
    cudaEvent_t evFork, evJoin;
    cudaEventCreateWithFlags(&evFork, cudaEventDisableTiming);
    cudaEventCreateWithFlags(&evJoin, cudaEventDisableTiming);

    cudaEventRecord(evFork, 0);
    cudaStreamWaitEvent(s2, evFork, 0);

    k_zero_deg<<<(n + 255) / 256, 256, 0, s2>>>(n);
    k_count<<<(E + 255) / 256, 256, 0, s2>>>(dst, E);
    int nb = (n + 511) / 512;
    k_scan1<<<nb, 512, 0, s2>>>(n);
    k_scan3b<<<nb, 512, 0, s2>>>(n, E, nb);
    k_scatter<<<(E + 255) / 256, 256, 0, s2>>>(src, dst, E);
    cudaEventRecord(evJoin, s2);

    k_prep_all<<<64 + (n * 32 + 255) / 256, 256>>>(x, ws1, wn1, ws2, wn2,
                                                   ws3, wn3, ws4, wn4, n);
    cudaStreamWaitEvent(0, evJoin, 0);

    // PDL chain; aggm persistent (single wave); h planes ping-pong between sets.
    launch_pdl(k_aggm, AGG_BLOCKS, 256, (size_t)0, n, pF + 0 * TILES, 0);
    launch_pdl(k_gemm_hid, tiles, 256, (size_t)SMEM, (const uint4*)(pB + 0 * 4096), b1,
               (const int*)(pF + 0 * TILES), 0, n);
    launch_pdl(k_aggm, AGG_BLOCKS, 256, (size_t)0, n, pF + 1 * TILES, 1);
    launch_pdl(k_gemm_hid, tiles, 256, (size_t)SMEM, (const uint4*)(pB + 1 * 4096), b2,
               (const int*)(pF + 1 * TILES), 1, n);
    launch_pdl(k_aggm, AGG_BLOCKS, 256, (size_t)0, n, pF + 2 * TILES, 0);
    launch_pdl(k_gemm_hid, tiles, 256, (size_t)SMEM, (const uint4*)(pB + 2 * 4096), b3,
               (const int*)(pF + 2 * TILES), 0, n);
    launch_pdl(k_gemm_fin, tiles, 256, (size_t)SMEM, (const uint4*)(pB + 3 * 4096), b4, n);
    launch_pdl(k_aggf, (n + 7) / 8, 256, (size_t)0, (const float*)b4, (float*)d_out, n);

    cudaEventDestroy(evFork);
    cudaEventDestroy(evJoin);
    cudaStreamDestroy(s2);
}

// round 14
// speedup vs baseline: 1.2697x; 1.2697x over previous
#include <cuda_runtime.h>
#include <cuda_fp16.h>

#define NN 100000
#define EE 1600000
#define TILES ((NN + 127) / 128)

// ---------------- scratch (static __device__, no allocation) ----------------
__device__ uint4 g_A[(size_t)TILES * 4 * 1024];   // per tile: h k0,h k64,m k0,m k64 planes
__device__ uint4 g_B[4 * 4 * 1024];               // per layer: 4 chunk planes, fp16
__device__ float g_s[(size_t)NN * 40];            // layer-4 self term, fp32
__device__ unsigned g_t[(size_t)NN * 24];         // layer-4 neigh term, fp16 (40 vals, pad 96B)
__device__ int   g_deg[NN];
__device__ int   g_rp[NN + 1];
__device__ int   g_cur[NN];
__device__ int   g_col[EE];
__device__ int   g_bsum[256];

// ---------------- helpers ----------------
__device__ __forceinline__ int swz(int x) { return x ^ ((x >> 3) & 0x70); }

__device__ __forceinline__ uint2 pack_h4(float4 v) {
    __half2 a = __floats2half2_rn(v.x, v.y);
    __half2 b = __floats2half2_rn(v.z, v.w);
    uint2 r;
    r.x = *(unsigned*)&a;
    r.y = *(unsigned*)&b;
    return r;
}

__device__ __forceinline__ unsigned smem_u32(const void* p) {
    unsigned a;
    asm("{ .reg .u64 t; cvta.to.shared.u64 t, %1; cvt.u32.u64 %0, t; }" : "=r"(a) : "l"(p));
    return a;
}
__device__ __forceinline__ void cp16(unsigned s, const void* g) {
    asm volatile("cp.async.cg.shared.global [%0], [%1], 16;" :: "r"(s), "l"(g));
}
__device__ __forceinline__ void cp_commit() { asm volatile("cp.async.commit_group;"); }
__device__ __forceinline__ void cp_wait0() { asm volatile("cp.async.wait_group 0;"); }
__device__ __forceinline__ void cp_wait1() { asm volatile("cp.async.wait_group 1;"); }
__device__ __forceinline__ void cp_wait2() { asm volatile("cp.async.wait_group 2;"); }

__device__ __forceinline__ void grid_wait() {
    asm volatile("griddepcontrol.wait;" ::: "memory");
}
__device__ __forceinline__ void grid_trigger() {
    asm volatile("griddepcontrol.launch_dependents;");
}

__device__ __forceinline__ void ldm_x4(unsigned* r, unsigned addr) {
    asm volatile("ldmatrix.sync.aligned.m8n8.x4.shared.b16 {%0,%1,%2,%3}, [%4];"
                 : "=r"(r[0]), "=r"(r[1]), "=r"(r[2]), "=r"(r[3]) : "r"(addr));
}
__device__ __forceinline__ void mma_f16(float* d, const unsigned* a, unsigned b0, unsigned b1) {
    asm volatile(
        "mma.sync.aligned.m16n8k16.row.col.f32.f16.f16.f32 "
        "{%0,%1,%2,%3}, {%4,%5,%6,%7}, {%8,%9}, {%0,%1,%2,%3};"
        : "+f"(d[0]), "+f"(d[1]), "+f"(d[2]), "+f"(d[3])
        : "r"(a[0]), "r"(a[1]), "r"(a[2]), "r"(a[3]), "r"(b0), "r"(b1));
}

__device__ __forceinline__ void mma_chunk(float acc[4][4][4], unsigned Ap, unsigned Bp,
                                          int arow, int brow, int lane) {
#pragma unroll
    for (int ks = 0; ks < 4; ks++) {
        unsigned afr[4][4];
        {
            int seg = ks * 2 + (lane >> 4);
            int inner = swz(((arow & 7) << 7) + seg * 16);
#pragma unroll
            for (int mt = 0; mt < 4; mt++)
                ldm_x4(afr[mt], Ap + (unsigned)((((arow >> 3) + 2 * mt) << 10) + inner));
        }
        unsigned bfr[2][4];
        {
            int seg = ks * 2 + ((lane >> 3) & 1);
            int inner = swz(((brow & 7) << 7) + seg * 16);
#pragma unroll
            for (int nb = 0; nb < 2; nb++)
                ldm_x4(bfr[nb], Bp + (unsigned)((((brow >> 3) + 2 * nb) << 10) + inner));
        }
#pragma unroll
        for (int mt = 0; mt < 4; mt++)
#pragma unroll
            for (int nt = 0; nt < 4; nt++)
                mma_f16(acc[mt][nt], afr[mt],
                        bfr[nt >> 1][(nt & 1) * 2], bfr[nt >> 1][(nt & 1) * 2 + 1]);
    }
}

// ---------------- prep: x -> fp16 planes (chunks 0,1) + all weights ----------------
__global__ void k_prep_all(const float* __restrict__ x,
                           const float* __restrict__ ws1, const float* __restrict__ wn1,
                           const float* __restrict__ ws2, const float* __restrict__ wn2,
                           const float* __restrict__ ws3, const float* __restrict__ wn3,
                           const float* __restrict__ ws4, const float* __restrict__ wn4,
                           int n) {
    int bx = blockIdx.x;
    if (bx < 64) {
        int layer = bx >> 4;
        int idx = (bx & 15) * 256 + threadIdx.x;   // 0..4095
        int f = idx >> 5, k = (idx & 31) << 2;
        int kb = (k & 63) << 1;
        int off = ((f >> 3) << 10) + swz(((f & 7) << 7) + kb);
        if (layer < 3) {
            const float* ws = (layer == 0) ? ws1 : (layer == 1) ? ws2 : ws3;
            const float* wn = (layer == 0) ? wn1 : (layer == 1) ? wn2 : wn3;
            float4 vs = *(const float4*)(ws + (size_t)f * 128 + k);
            float4 vn = *(const float4*)(wn + (size_t)f * 128 + k);
            int chunk = k >> 6;
            char* b0 = (char*)g_B + ((size_t)layer * 4 + chunk) * 16384;
            char* b1 = (char*)g_B + ((size_t)layer * 4 + chunk + 2) * 16384;
            *(uint2*)(b0 + off) = pack_h4(vs);
            *(uint2*)(b1 + off) = pack_h4(vn);
        } else {
            float4 v = make_float4(0.f, 0.f, 0.f, 0.f);
            if (f < 40) v = *(const float4*)(ws4 + (size_t)f * 128 + k);
            else if (f < 80) v = *(const float4*)(wn4 + (size_t)(f - 40) * 128 + k);
            int chunk = k >> 6;
            char* b0 = (char*)g_B + ((size_t)3 * 4 + chunk) * 16384;
            *(uint2*)(b0 + off) = pack_h4(v);
        }
        return;
    }
    int idx = (bx - 64) * 256 + threadIdx.x;
    if (idx >= n * 32) return;
    int node = idx >> 5, k = (idx & 31) << 2;
    float4 v = *(const float4*)(x + (size_t)node * 128 + k);
    uint2 q = pack_h4(v);
    int tile = node >> 7, r = node & 127, chunk = k >> 6, kb = (k & 63) << 1;
    char* base = (char*)g_A + ((size_t)tile * 4 + chunk) * 16384;
    int off = ((r >> 3) << 10) + swz(((r & 7) << 7) + kb);
    *(uint2*)(base + off) = q;
}

// ---------------- CSR build (side stream; deg zeroed by memset) ----------------
__global__ void k_count(const int* __restrict__ dst, int e) {
    int i = blockIdx.x * blockDim.x + threadIdx.x;
    if (i < e) atomicAdd(&g_deg[dst[i]], 1);
}
__global__ void k_scan1(int n) {
    __shared__ int s[512];
    int i = blockIdx.x * 512 + threadIdx.x;
    int v = (i < n) ? g_deg[i] : 0;
    s[threadIdx.x] = v;
    __syncthreads();
    for (int off = 1; off < 512; off <<= 1) {
        int t = (threadIdx.x >= off) ? s[threadIdx.x - off] : 0;
        __syncthreads();
        s[threadIdx.x] += t;
        __syncthreads();
    }
    if (i < n) g_rp[i] = s[threadIdx.x] - v;
    if (threadIdx.x == 511) g_bsum[blockIdx.x] = s[511];
}
__global__ void k_scan3b(int n, int e, int nb) {
    __shared__ int s[512];
    int tid = threadIdx.x, bid = blockIdx.x;
    s[tid] = (tid < nb && tid < bid) ? g_bsum[tid] : 0;
    __syncthreads();
    for (int off = 256; off >= 1; off >>= 1) {
        if (tid < off) s[tid] += s[tid + off];
        __syncthreads();
    }
    int offv = s[0];
    int i = bid * 512 + tid;
    if (i < n) {
        int r = g_rp[i] + offv;
        g_rp[i] = r;
        g_cur[i] = r;
    }
    if (i == 0) g_rp[n] = e;
}
__global__ void k_scatter(const int* __restrict__ src, const int* __restrict__ dst, int e) {
    int i = blockIdx.x * blockDim.x + threadIdx.x;
    if (i < e) {
        int d = dst[i];
        int p = atomicAdd(&g_cur[d], 1);
        g_col[p] = src[i];
    }
}

// ---------------- aggregation: m[v] = mean_in h[src] (fp16 planes -> m planes) ----------------
// Triggers dependent gemm launch at entry; gemm grid_wait()s before m use.
__global__ __launch_bounds__(256)
void k_aggm(int n) {
    if (threadIdx.x == 0) grid_trigger();
    int w = (blockIdx.x * 256 + threadIdx.x) >> 5;
    int lane = threadIdx.x & 31;
    if (w >= n) return;
    int beg = g_rp[w], end = g_rp[w + 1];

    const int chunk = lane >> 4, kb = (lane & 15) << 3;
    const char* Ab = (const char*)g_A;

    float4 acc = make_float4(0.f, 0.f, 0.f, 0.f);
    for (int e = beg; e < end; e += 4) {
        int i1 = min(e + 1, end - 1);
        int i2 = min(e + 2, end - 1);
        int i3 = min(e + 3, end - 1);
        int u0 = g_col[e], u1 = g_col[i1], u2 = g_col[i2], u3 = g_col[i3];
#define ROWADDR(u) (Ab + ((size_t)((u >> 7) * 4 + chunk)) * 16384 + \
                    (((u & 127) >> 3) << 10) + swz((((u & 127) & 7) << 7) + kb))
        uint2 q0 = *(const uint2*)ROWADDR(u0);
        uint2 q1 = *(const uint2*)ROWADDR(u1);
        uint2 q2 = *(const uint2*)ROWADDR(u2);
        uint2 q3 = *(const uint2*)ROWADDR(u3);
#undef ROWADDR
#define ACC4(q) do { \
        float2 f0 = __half22float2(*(__half2*)&(q).x); \
        float2 f1 = __half22float2(*(__half2*)&(q).y); \
        acc.x += f0.x; acc.y += f0.y; acc.z += f1.x; acc.w += f1.y; } while (0)
        ACC4(q0);
        if (e + 1 < end) ACC4(q1);
        if (e + 2 < end) ACC4(q2);
        if (e + 3 < end) ACC4(q3);
#undef ACC4
    }
    float inv = 1.0f / (float)max(end - beg, 1);
    acc.x *= inv; acc.y *= inv; acc.z *= inv; acc.w *= inv;

    int tile = w >> 7, r = w & 127;
    char* base = (char*)g_A + ((size_t)tile * 4 + 2 + chunk) * 16384;
    int off = ((r >> 3) << 10) + swz(((r & 7) << 7) + kb);
    *(uint2*)(base + off) = pack_h4(acc);
}

// ---------------- GEMM pieces ----------------
// load one 16KB plane to smem offset
__device__ __forceinline__ void pf_plane(unsigned sbase, unsigned off, const uint4* src, int tid) {
    unsigned d = sbase + off;
#pragma unroll
    for (int i = 0; i < 4; i++) cp16(d + (tid + i * 256) * 16, src + tid + i * 256);
}

// hidden layers: PDL-split; 96KB smem. Phase 1 prefetches H0,W0 / H1,W1 / W2,W3
// (weights for phase 2 pre-staged!). After grid_wait only M planes load.
__global__ __launch_bounds__(256, 2)
void k_gemm_hid(const uint4* __restrict__ Bw, const float* __restrict__ bias, int n) {
    extern __shared__ char smem[];
    const int tid = threadIdx.x, wid = tid >> 5, lane = tid & 31;
    const int mh = wid >> 2, nq = wid & 3;
    const size_t tile = blockIdx.x;
    const unsigned sbase = smem_u32(smem);
    const uint4* gAt = g_A + tile * 4 * 1024;

    // slots (16KB each): S0=A0, S1=B0, S2=A1, S3=B1, S4=W2, S5=W3
    const unsigned S0 = 0u, S1 = 16384u, S2 = 32768u, S3 = 49152u, S4 = 65536u, S5 = 81920u;

    float acc[4][4][4];
#pragma unroll
    for (int a = 0; a < 4; a++)
#pragma unroll
        for (int b = 0; b < 4; b++)
#pragma unroll
            for (int c = 0; c < 4; c++) acc[a][b][c] = 0.f;

    const int arow = mh * 64 + (lane & 15);
    const int brow = nq * 32 + ((lane >> 4) << 3) + (lane & 7);

    // phase 1 prefetch: G0 = {H0,W0}, G1 = {H1,W1}, G2 = {W2,W3}
    pf_plane(sbase, S0, gAt, tid);
    pf_plane(sbase, S1, Bw, tid);
    cp_commit();
    pf_plane(sbase, S2, gAt + 1024, tid);
    pf_plane(sbase, S3, Bw + 1024, tid);
    cp_commit();
    pf_plane(sbase, S4, Bw + 2048, tid);
    pf_plane(sbase, S5, Bw + 3072, tid);
    cp_commit();

    cp_wait2();          // G0 done
    __syncthreads();
    mma_chunk(acc, sbase + S0, sbase + S1, arow, brow, lane);
    cp_wait1();          // G1 done
    __syncthreads();
    mma_chunk(acc, sbase + S2, sbase + S3, arow, brow, lane);
    __syncthreads();     // all reads of S0/S2 complete before overwrite

    // phase 2: m chunks (require aggm grid completion); weights already staged
    grid_wait();
    pf_plane(sbase, S0, gAt + 2048, tid);   // M0
    cp_commit();
    pf_plane(sbase, S2, gAt + 3072, tid);   // M1
    cp_commit();

    cp_wait1();          // M0 done (also guarantees G2)
    __syncthreads();
    mma_chunk(acc, sbase + S0, sbase + S4, arow, brow, lane);
    cp_wait0();          // M1 done
    __syncthreads();
    mma_chunk(acc, sbase + S2, sbase + S5, arow, brow, lane);
    __syncthreads();

    // epilogue
    const size_t base = tile * 128;
    const int rr = lane >> 2, cc = (lane & 3) * 2;
    __half* stg = (__half*)smem;   // stride 132 halves
#pragma unroll
    for (int mt = 0; mt < 4; mt++)
#pragma unroll
        for (int nt = 0; nt < 4; nt++) {
            int r = mh * 64 + mt * 16 + rr;
            int col = nq * 32 + nt * 8 + cc;
            float bv0 = __ldg(bias + col), bv1 = __ldg(bias + col + 1);
            float v0 = fmaxf(acc[mt][nt][0] + bv0, 0.f);
            float v1 = fmaxf(acc[mt][nt][1] + bv1, 0.f);
            float v2 = fmaxf(acc[mt][nt][2] + bv0, 0.f);
            float v3 = fmaxf(acc[mt][nt][3] + bv1, 0.f);
            *(__half2*)(stg + r * 132 + col) = __floats2half2_rn(v0, v1);
            *(__half2*)(stg + (r + 8) * 132 + col) = __floats2half2_rn(v2, v3);
        }
    __syncthreads();
    for (int t = tid; t < 4096; t += 256) {
        int nn = t >> 5, g = t & 31;
        size_t gn = base + nn;
        if (gn < (size_t)n) {
            uint2 q = *(uint2*)(stg + nn * 132 + g * 4);
            int k0 = g * 4;
            int chunk = k0 >> 6, kb = (k0 & 63) << 1;
            char* bA = (char*)g_A + (tile * 4 + chunk) * 16384;
            int off = ((nn >> 3) << 10) + swz(((nn & 7) << 7) + kb);
            *(uint2*)(bA + off) = q;
        }
    }
}

// final layer: st = [Ws4;Wn4] h3 over K=128 (chunks 0,1). Entry wait.
__global__ __launch_bounds__(256, 2)
void k_gemm_fin(const uint4* __restrict__ Bw, const float* __restrict__ bias, int n) {
    grid_wait();
    extern __shared__ char smem[];
    const int tid = threadIdx.x, wid = tid >> 5, lane = tid & 31;
    const int mh = wid >> 2, nq = wid & 3;
    const size_t tile = blockIdx.x;
    const unsigned sbase = smem_u32(smem);
    const uint4* gAt = g_A + tile * 4 * 1024;

    float acc[4][4][4];
#pragma unroll
    for (int a = 0; a < 4; a++)
#pragma unroll
        for (int b = 0; b < 4; b++)
#pragma unroll
            for (int c = 0; c < 4; c++) acc[a][b][c] = 0.f;

    const int arow = mh * 64 + (lane & 15);
    const int brow = nq * 32 + ((lane >> 4) << 3) + (lane & 7);

    pf_plane(sbase, 0u, gAt, tid);
    pf_plane(sbase, 16384u, Bw, tid);
    cp_commit();
    pf_plane(sbase, 32768u, gAt + 1024, tid);
    pf_plane(sbase, 49152u, Bw + 1024, tid);
    cp_commit();

    cp_wait1();
    __syncthreads();
    mma_chunk(acc, sbase, sbase + 16384u, arow, brow, lane);
    cp_wait0();
    __syncthreads();
    mma_chunk(acc, sbase + 32768u, sbase + 49152u, arow, brow, lane);
    __syncthreads();

    const size_t base = tile * 128;
    const int rr = lane >> 2, cc = (lane & 3) * 2;
    float* stage = (float*)smem;   // stride 84 floats, cols 0..79
#pragma unroll
    for (int mt = 0; mt < 4; mt++)
#pragma unroll
        for (int nt = 0; nt < 4; nt++) {
            int col = nq * 32 + nt * 8 + cc;
            if (col < 80) {
                int r = mh * 64 + mt * 16 + rr;
                stage[r * 84 + col] = acc[mt][nt][0];
                stage[r * 84 + col + 1] = acc[mt][nt][1];
                stage[(r + 8) * 84 + col] = acc[mt][nt][2];
                stage[(r + 8) * 84 + col + 1] = acc[mt][nt][3];
            }
        }
    __syncthreads();
    for (int t = tid; t < 128 * 10; t += 256) {
        int nn = t / 10, c4 = t % 10;
        size_t gn = base + nn;
        if (gn < (size_t)n)
            *(float4*)(g_s + gn * 40 + c4 * 4) = *(float4*)(stage + nn * 84 + c4 * 4);
    }
    for (int t = tid; t < 128 * 20; t += 256) {
        int nn = t / 20, j = t % 20;
        size_t gn = base + nn;
        if (gn < (size_t)n) {
            __half2 h = __floats2half2_rn(stage[nn * 84 + 40 + 2 * j],
                                          stage[nn * 84 + 41 + 2 * j]);
            g_t[gn * 24 + j] = *(unsigned*)&h;
        }
    }
}

// ---------------- final aggregation: out[v] = s[v] + mean_t + b (fp16 gather) ----------------
__global__ __launch_bounds__(256)
void k_aggf(const float* __restrict__ b, float* __restrict__ out, int n) {
    grid_wait();
    int w = (blockIdx.x * 256 + threadIdx.x) >> 5;
    int lane = threadIdx.x & 31;
    if (w >= n) return;
    int beg = g_rp[w], end = g_rp[w + 1];

    const int l = min(lane, 19);
    float2 acc = make_float2(0.f, 0.f);
    for (int e = beg; e < end; e += 2) {
        int i1 = min(e + 1, end - 1);
        int u0 = g_col[e], u1 = g_col[i1];
        unsigned q0 = g_t[(size_t)u0 * 24 + l];
        unsigned q1 = g_t[(size_t)u1 * 24 + l];
        if (lane < 20) {
            float2 f0 = __half22float2(*(__half2*)&q0);
            acc.x += f0.x; acc.y += f0.y;
            if (e + 1 < end) {
                float2 f1 = __half22float2(*(__half2*)&q1);
                acc.x += f1.x; acc.y += f1.y;
            }
        }
    }
    if (lane < 20) {
        float inv = 1.0f / (float)max(end - beg, 1);
        float2 s = *(const float2*)(g_s + (size_t)w * 40 + 2 * lane);
        float2 bb = *(const float2*)(b + 2 * lane);
        float2 r;
        r.x = fmaf(acc.x, inv, s.x + bb.x);
        r.y = fmaf(acc.y, inv, s.y + bb.y);
        *(float2*)(out + (size_t)w * 40 + 2 * lane) = r;
    }
}

// ---------------- PDL launch helper ----------------
template <typename K, typename... Args>
static void launch_pdl(K kern, int grid, int block, size_t smem, Args... args) {
    cudaLaunchConfig_t cfg = {};
    cfg.gridDim = dim3(grid, 1, 1);
    cfg.blockDim = dim3(block, 1, 1);
    cfg.dynamicSmemBytes = smem;
    cfg.stream = 0;
    cudaLaunchAttribute attr[1];
    attr[0].id = cudaLaunchAttributeProgrammaticStreamSerialization;
    attr[0].val.programmaticStreamSerializationAllowed = 1;
    cfg.attrs = attr;
    cfg.numAttrs = 1;
    cudaLaunchKernelEx(&cfg, kern, args...);
}

// ---------------- launch ----------------
extern "C" void kernel_launch(void* const* d_in, const int* in_sizes, int n_in,
                              void* d_out, int out_size) {
    const float* x   = (const float*)d_in[0];
    const int*   src = (const int*)d_in[1];
    const int*   dst = (const int*)d_in[2];
    const float* ws1 = (const float*)d_in[3];
    const float* wn1 = (const float*)d_in[4];
    const float* b1  = (const float*)d_in[5];
    const float* ws2 = (const float*)d_in[6];
    const float* wn2 = (const float*)d_in[7];
    const float* b2  = (const float*)d_in[8];
    const float* ws3 = (const float*)d_in[9];
    const float* wn3 = (const float*)d_in[10];
    const float* b3  = (const float*)d_in[11];
    const float* ws4 = (const float*)d_in[12];
    const float* wn4 = (const float*)d_in[13];
    const float* b4  = (const float*)d_in[14];

    const int n = in_sizes[0] / 128;
    const int E = in_sizes[1];
    const int tiles = (n + 127) / 128;

    const int SMEM_H = 96 * 1024;
    const int SMEM_F = 64 * 1024;
    cudaFuncSetAttribute(k_gemm_hid, cudaFuncAttributeMaxDynamicSharedMemorySize, SMEM_H);
    cudaFuncSetAttribute(k_gemm_fin, cudaFuncAttributeMaxDynamicSharedMemorySize, SMEM_F);

    uint4* pB;
    int* pDeg;
    cudaGetSymbolAddress((void**)&pB, g_B);
    cudaGetSymbolAddress((void**)&pDeg, g_deg);

    // fork: CSR chain on a side stream, overlapped with preps
    cudaStream_t s2;
    cudaStreamCreateWithFlags(&s2, cudaStreamNonBlocking);
    cudaEvent_t evFork, evJoin;
    cudaEventCreateWithFlags(&evFork, cudaEventDisableTiming);
    cudaEventCreateWithFlags(&evJoin, cudaEventDisableTiming);

    cudaEventRecord(evFork, 0);
    cudaStreamWaitEvent(s2, evFork, 0);

    cudaMemsetAsync(pDeg, 0, (size_t)n * sizeof(int), s2);
    k_count<<<(E + 255) / 256, 256, 0, s2>>>(dst, E);
    int nb = (n + 511) / 512;
    k_scan1<<<nb, 512, 0, s2>>>(n);
    k_scan3b<<<nb, 512, 0, s2>>>(n, E, nb);
    k_scatter<<<(E + 255) / 256, 256, 0, s2>>>(src, dst, E);
    cudaEventRecord(evJoin, s2);

    k_prep_all<<<64 + (n * 32 + 255) / 256, 256>>>(x, ws1, wn1, ws2, wn2,
                                                   ws3, wn3, ws4, wn4, n);
    cudaStreamWaitEvent(0, evJoin, 0);

    const int ga = (n + 7) / 8;

    // L1..L3: aggm triggers; gemm (PDL) overlaps h-phase with aggm tail
    k_aggm<<<ga, 256>>>(n);
    launch_pdl(k_gemm_hid, tiles, 256, (size_t)SMEM_H, (const uint4*)(pB + 0 * 4096), b1, n);
    k_aggm<<<ga, 256>>>(n);
    launch_pdl(k_gemm_hid, tiles, 256, (size_t)SMEM_H, (const uint4*)(pB + 1 * 4096), b2, n);
    k_aggm<<<ga, 256>>>(n);
    launch_pdl(k_gemm_hid, tiles, 256, (size_t)SMEM_H, (const uint4*)(pB + 2 * 4096), b3, n);
    // L4 + final gather
    launch_pdl(k_gemm_fin, tiles, 256, (size_t)SMEM_F, (const uint4*)(pB + 3 * 4096), b4, n);
    launch_pdl(k_aggf, ga, 256, (size_t)0, (const float*)b4, (float*)d_out, n);

    cudaEventDestroy(evFork);
    cudaEventDestroy(evJoin);
    cudaStreamDestroy(s2);
}

// round 15
// speedup vs baseline: 1.3881x; 1.0932x over previous
#include <cuda_runtime.h>
#include <cuda_fp16.h>

#define NN 100000
#define EE 1600000
#define TILES ((NN + 127) / 128)

// ---------------- scratch (static __device__, no allocation) ----------------
__device__ uint4 g_A[(size_t)TILES * 4 * 1024];   // per tile: h k0,h k64,m k0,m k64 planes
__device__ uint4 g_B[4 * 4 * 1024];               // per layer: 4 chunk planes, fp16
__device__ float g_s[(size_t)NN * 40];            // layer-4 self term, fp32
__device__ unsigned g_t[(size_t)NN * 24];         // layer-4 neigh term, fp16 (40 vals, pad 96B)
__device__ int   g_deg[NN];
__device__ int   g_rp[NN + 1];
__device__ int   g_cur[NN];
__device__ int   g_col[EE];
__device__ int   g_bsum[256];

// ---------------- helpers ----------------
__device__ __forceinline__ int swz(int x) { return x ^ ((x >> 3) & 0x70); }

__device__ __forceinline__ uint2 pack_h4(float4 v) {
    __half2 a = __floats2half2_rn(v.x, v.y);
    __half2 b = __floats2half2_rn(v.z, v.w);
    uint2 r;
    r.x = *(unsigned*)&a;
    r.y = *(unsigned*)&b;
    return r;
}

__device__ __forceinline__ unsigned smem_u32(const void* p) {
    unsigned a;
    asm("{ .reg .u64 t; cvta.to.shared.u64 t, %1; cvt.u32.u64 %0, t; }" : "=r"(a) : "l"(p));
    return a;
}
__device__ __forceinline__ void cp16(unsigned s, const void* g) {
    asm volatile("cp.async.cg.shared.global [%0], [%1], 16;" :: "r"(s), "l"(g));
}
__device__ __forceinline__ void cp_commit() { asm volatile("cp.async.commit_group;"); }
__device__ __forceinline__ void cp_wait0() { asm volatile("cp.async.wait_group 0;"); }
__device__ __forceinline__ void cp_wait1() { asm volatile("cp.async.wait_group 1;"); }
__device__ __forceinline__ void cp_wait2() { asm volatile("cp.async.wait_group 2;"); }

__device__ __forceinline__ void grid_wait() {
    asm volatile("griddepcontrol.wait;" ::: "memory");
}
__device__ __forceinline__ void grid_trigger() {
    asm volatile("griddepcontrol.launch_dependents;");
}

__device__ __forceinline__ void ldm_x4(unsigned* r, unsigned addr) {
    asm volatile("ldmatrix.sync.aligned.m8n8.x4.shared.b16 {%0,%1,%2,%3}, [%4];"
                 : "=r"(r[0]), "=r"(r[1]), "=r"(r[2]), "=r"(r[3]) : "r"(addr));
}
__device__ __forceinline__ void mma_f16(float* d, const unsigned* a, unsigned b0, unsigned b1) {
    asm volatile(
        "mma.sync.aligned.m16n8k16.row.col.f32.f16.f16.f32 "
        "{%0,%1,%2,%3}, {%4,%5,%6,%7}, {%8,%9}, {%0,%1,%2,%3};"
        : "+f"(d[0]), "+f"(d[1]), "+f"(d[2]), "+f"(d[3])
        : "r"(a[0]), "r"(a[1]), "r"(a[2]), "r"(a[3]), "r"(b0), "r"(b1));
}

__device__ __forceinline__ void mma_chunk(float acc[4][4][4], unsigned Ap, unsigned Bp,
                                          int arow, int brow, int lane) {
#pragma unroll
    for (int ks = 0; ks < 4; ks++) {
        unsigned afr[4][4];
        {
            int seg = ks * 2 + (lane >> 4);
            int inner = swz(((arow & 7) << 7) + seg * 16);
#pragma unroll
            for (int mt = 0; mt < 4; mt++)
                ldm_x4(afr[mt], Ap + (unsigned)((((arow >> 3) + 2 * mt) << 10) + inner));
        }
        unsigned bfr[2][4];
        {
            int seg = ks * 2 + ((lane >> 3) & 1);
            int inner = swz(((brow & 7) << 7) + seg * 16);
#pragma unroll
            for (int nb = 0; nb < 2; nb++)
                ldm_x4(bfr[nb], Bp + (unsigned)((((brow >> 3) + 2 * nb) << 10) + inner));
        }
#pragma unroll
        for (int mt = 0; mt < 4; mt++)
#pragma unroll
            for (int nt = 0; nt < 4; nt++)
                mma_f16(acc[mt][nt], afr[mt],
                        bfr[nt >> 1][(nt & 1) * 2], bfr[nt >> 1][(nt & 1) * 2 + 1]);
    }
}

// ---------------- prep: x -> fp16 planes (chunks 0,1) + all weights ----------------
__global__ void k_prep_all(const float* __restrict__ x,
                           const float* __restrict__ ws1, const float* __restrict__ wn1,
                           const float* __restrict__ ws2, const float* __restrict__ wn2,
                           const float* __restrict__ ws3, const float* __restrict__ wn3,
                           const float* __restrict__ ws4, const float* __restrict__ wn4,
                           int n) {
    int bx = blockIdx.x;
    if (bx < 64) {
        int layer = bx >> 4;
        int idx = (bx & 15) * 256 + threadIdx.x;   // 0..4095
        int f = idx >> 5, k = (idx & 31) << 2;
        int kb = (k & 63) << 1;
        int off = ((f >> 3) << 10) + swz(((f & 7) << 7) + kb);
        if (layer < 3) {
            const float* ws = (layer == 0) ? ws1 : (layer == 1) ? ws2 : ws3;
            const float* wn = (layer == 0) ? wn1 : (layer == 1) ? wn2 : wn3;
            float4 vs = *(const float4*)(ws + (size_t)f * 128 + k);
            float4 vn = *(const float4*)(wn + (size_t)f * 128 + k);
            int chunk = k >> 6;
            char* b0 = (char*)g_B + ((size_t)layer * 4 + chunk) * 16384;
            char* b1 = (char*)g_B + ((size_t)layer * 4 + chunk + 2) * 16384;
            *(uint2*)(b0 + off) = pack_h4(vs);
            *(uint2*)(b1 + off) = pack_h4(vn);
        } else {
            float4 v = make_float4(0.f, 0.f, 0.f, 0.f);
            if (f < 40) v = *(const float4*)(ws4 + (size_t)f * 128 + k);
            else if (f < 80) v = *(const float4*)(wn4 + (size_t)(f - 40) * 128 + k);
            int chunk = k >> 6;
            char* b0 = (char*)g_B + ((size_t)3 * 4 + chunk) * 16384;
            *(uint2*)(b0 + off) = pack_h4(v);
        }
        return;
    }
    int idx = (bx - 64) * 256 + threadIdx.x;
    if (idx >= n * 32) return;
    int node = idx >> 5, k = (idx & 31) << 2;
    float4 v = *(const float4*)(x + (size_t)node * 128 + k);
    uint2 q = pack_h4(v);
    int tile = node >> 7, r = node & 127, chunk = k >> 6, kb = (k & 63) << 1;
    char* base = (char*)g_A + ((size_t)tile * 4 + chunk) * 16384;
    int off = ((r >> 3) << 10) + swz(((r & 7) << 7) + kb);
    *(uint2*)(base + off) = q;
}

// ---------------- CSR build (side stream; deg zeroed by memset) ----------------
// 4 edges/thread (int4 load) => 4 independent atomic chains per thread.
__global__ void k_count(const int* __restrict__ dst, int e) {
    int i0 = (blockIdx.x * 256 + threadIdx.x) * 4;
    if (i0 + 3 < e) {
        int4 d = *(const int4*)(dst + i0);
        atomicAdd(&g_deg[d.x], 1);
        atomicAdd(&g_deg[d.y], 1);
        atomicAdd(&g_deg[d.z], 1);
        atomicAdd(&g_deg[d.w], 1);
    } else {
        for (int j = 0; j < 4; j++)
            if (i0 + j < e) atomicAdd(&g_deg[dst[i0 + j]], 1);
    }
}
__global__ void k_scan1(int n) {
    __shared__ int s[512];
    int i = blockIdx.x * 512 + threadIdx.x;
    int v = (i < n) ? g_deg[i] : 0;
    s[threadIdx.x] = v;
    __syncthreads();
    for (int off = 1; off < 512; off <<= 1) {
        int t = (threadIdx.x >= off) ? s[threadIdx.x - off] : 0;
        __syncthreads();
        s[threadIdx.x] += t;
        __syncthreads();
    }
    if (i < n) g_rp[i] = s[threadIdx.x] - v;
    if (threadIdx.x == 511) g_bsum[blockIdx.x] = s[511];
}
__global__ void k_scan3b(int n, int e, int nb) {
    __shared__ int s[512];
    int tid = threadIdx.x, bid = blockIdx.x;
    s[tid] = (tid < nb && tid < bid) ? g_bsum[tid] : 0;
    __syncthreads();
    for (int off = 256; off >= 1; off >>= 1) {
        if (tid < off) s[tid] += s[tid + off];
        __syncthreads();
    }
    int offv = s[0];
    int i = bid * 512 + tid;
    if (i < n) {
        int r = g_rp[i] + offv;
        g_rp[i] = r;
        g_cur[i] = r;
    }
    if (i == 0) g_rp[n] = e;
}
// 4 edges/thread: int4 loads of dst+src, 4 independent atomic->store chains.
__global__ void k_scatter(const int* __restrict__ src, const int* __restrict__ dst, int e) {
    int i0 = (blockIdx.x * 256 + threadIdx.x) * 4;
    if (i0 + 3 < e) {
        int4 d = *(const int4*)(dst + i0);
        int4 s = *(const int4*)(src + i0);
        int p0 = atomicAdd(&g_cur[d.x], 1);
        int p1 = atomicAdd(&g_cur[d.y], 1);
        int p2 = atomicAdd(&g_cur[d.z], 1);
        int p3 = atomicAdd(&g_cur[d.w], 1);
        g_col[p0] = s.x;
        g_col[p1] = s.y;
        g_col[p2] = s.z;
        g_col[p3] = s.w;
    } else {
        for (int j = 0; j < 4; j++) {
            int i = i0 + j;
            if (i < e) {
                int p = atomicAdd(&g_cur[dst[i]], 1);
                g_col[p] = src[i];
            }
        }
    }
}

// ---------------- aggregation: m[v] = mean_in h[src] (fp16 planes -> m planes) ----------------
// Triggers dependent gemm launch at entry; gemm grid_wait()s before m use.
// Tail loads predicated (no redundant gather traffic).
__global__ __launch_bounds__(256)
void k_aggm(int n) {
    if (threadIdx.x == 0) grid_trigger();
    int w = (blockIdx.x * 256 + threadIdx.x) >> 5;
    int lane = threadIdx.x & 31;
    if (w >= n) return;
    int beg = g_rp[w], end = g_rp[w + 1];

    const int chunk = lane >> 4, kb = (lane & 15) << 3;
    const char* Ab = (const char*)g_A;

    float4 acc = make_float4(0.f, 0.f, 0.f, 0.f);
#define ROWADDR(u) (Ab + ((size_t)((u >> 7) * 4 + chunk)) * 16384 + \
                    (((u & 127) >> 3) << 10) + swz((((u & 127) & 7) << 7) + kb))
#define ACC4(q) do { \
        float2 f0 = __half22float2(*(__half2*)&(q).x); \
        float2 f1 = __half22float2(*(__half2*)&(q).y); \
        acc.x += f0.x; acc.y += f0.y; acc.z += f1.x; acc.w += f1.y; } while (0)
    int e = beg;
    for (; e + 4 <= end; e += 4) {
        int u0 = g_col[e], u1 = g_col[e + 1], u2 = g_col[e + 2], u3 = g_col[e + 3];
        uint2 q0 = *(const uint2*)ROWADDR(u0);
        uint2 q1 = *(const uint2*)ROWADDR(u1);
        uint2 q2 = *(const uint2*)ROWADDR(u2);
        uint2 q3 = *(const uint2*)ROWADDR(u3);
        ACC4(q0);
        ACC4(q1);
        ACC4(q2);
        ACC4(q3);
    }
    for (; e < end; e++) {
        int u0 = g_col[e];
        uint2 q0 = *(const uint2*)ROWADDR(u0);
        ACC4(q0);
    }
#undef ACC4
#undef ROWADDR
    float inv = 1.0f / (float)max(end - beg, 1);
    acc.x *= inv; acc.y *= inv; acc.z *= inv; acc.w *= inv;

    int tile = w >> 7, r = w & 127;
    char* base = (char*)g_A + ((size_t)tile * 4 + 2 + chunk) * 16384;
    int off = ((r >> 3) << 10) + swz(((r & 7) << 7) + kb);
    *(uint2*)(base + off) = pack_h4(acc);
}

// ---------------- GEMM pieces ----------------
__device__ __forceinline__ void pf_plane(unsigned sbase, unsigned off, const uint4* src, int tid) {
    unsigned d = sbase + off;
#pragma unroll
    for (int i = 0; i < 4; i++) cp16(d + (tid + i * 256) * 16, src + tid + i * 256);
}

// hidden layers: PDL-split; 96KB smem; phase-2 weights pre-staged in phase 1.
__global__ __launch_bounds__(256, 2)
void k_gemm_hid(const uint4* __restrict__ Bw, const float* __restrict__ bias, int n) {
    extern __shared__ char smem[];
    const int tid = threadIdx.x, wid = tid >> 5, lane = tid & 31;
    const int mh = wid >> 2, nq = wid & 3;
    const size_t tile = blockIdx.x;
    const unsigned sbase = smem_u32(smem);
    const uint4* gAt = g_A + tile * 4 * 1024;

    const unsigned S0 = 0u, S1 = 16384u, S2 = 32768u, S3 = 49152u, S4 = 65536u, S5 = 81920u;

    float acc[4][4][4];
#pragma unroll
    for (int a = 0; a < 4; a++)
#pragma unroll
        for (int b = 0; b < 4; b++)
#pragma unroll
            for (int c = 0; c < 4; c++) acc[a][b][c] = 0.f;

    const int arow = mh * 64 + (lane & 15);
    const int brow = nq * 32 + ((lane >> 4) << 3) + (lane & 7);

    pf_plane(sbase, S0, gAt, tid);
    pf_plane(sbase, S1, Bw, tid);
    cp_commit();
    pf_plane(sbase, S2, gAt + 1024, tid);
    pf_plane(sbase, S3, Bw + 1024, tid);
    cp_commit();
    pf_plane(sbase, S4, Bw + 2048, tid);
    pf_plane(sbase, S5, Bw + 3072, tid);
    cp_commit();

    cp_wait2();
    __syncthreads();
    mma_chunk(acc, sbase + S0, sbase + S1, arow, brow, lane);
    cp_wait1();
    __syncthreads();
    mma_chunk(acc, sbase + S2, sbase + S3, arow, brow, lane);
    __syncthreads();

    grid_wait();
    pf_plane(sbase, S0, gAt + 2048, tid);   // M0
    cp_commit();
    pf_plane(sbase, S2, gAt + 3072, tid);   // M1
    cp_commit();

    cp_wait1();
    __syncthreads();
    mma_chunk(acc, sbase + S0, sbase + S4, arow, brow, lane);
    cp_wait0();
    __syncthreads();
    mma_chunk(acc, sbase + S2, sbase + S5, arow, brow, lane);
    __syncthreads();

    const size_t base = tile * 128;
    const int rr = lane >> 2, cc = (lane & 3) * 2;
    __half* stg = (__half*)smem;   // stride 132 halves
#pragma unroll
    for (int mt = 0; mt < 4; mt++)
#pragma unroll
        for (int nt = 0; nt < 4; nt++) {
            int r = mh * 64 + mt * 16 + rr;
            int col = nq * 32 + nt * 8 + cc;
            float bv0 = __ldg(bias + col), bv1 = __ldg(bias + col + 1);
            float v0 = fmaxf(acc[mt][nt][0] + bv0, 0.f);
            float v1 = fmaxf(acc[mt][nt][1] + bv1, 0.f);
            float v2 = fmaxf(acc[mt][nt][2] + bv0, 0.f);
            float v3 = fmaxf(acc[mt][nt][3] + bv1, 0.f);
            *(__half2*)(stg + r * 132 + col) = __floats2half2_rn(v0, v1);
            *(__half2*)(stg + (r + 8) * 132 + col) = __floats2half2_rn(v2, v3);
        }
    __syncthreads();
    for (int t = tid; t < 4096; t += 256) {
        int nn = t >> 5, g = t & 31;
        size_t gn = base + nn;
        if (gn < (size_t)n) {
            uint2 q = *(uint2*)(stg + nn * 132 + g * 4);
            int k0 = g * 4;
            int chunk = k0 >> 6, kb = (k0 & 63) << 1;
            char* bA = (char*)g_A + (tile * 4 + chunk) * 16384;
            int off = ((nn >> 3) << 10) + swz(((nn & 7) << 7) + kb);
            *(uint2*)(bA + off) = q;
        }
    }
}

// final layer: st = [Ws4;Wn4] h3 over K=128 (chunks 0,1). Entry wait.
__global__ __launch_bounds__(256, 2)
void k_gemm_fin(const uint4* __restrict__ Bw, const float* __restrict__ bias, int n) {
    grid_wait();
    extern __shared__ char smem[];
    const int tid = threadIdx.x, wid = tid >> 5, lane = tid & 31;
    const int mh = wid >> 2, nq = wid & 3;
    const size_t tile = blockIdx.x;
    const unsigned sbase = smem_u32(smem);
    const uint4* gAt = g_A + tile * 4 * 1024;

    float acc[4][4][4];
#pragma unroll
    for (int a = 0; a < 4; a++)
#pragma unroll
        for (int b = 0; b < 4; b++)
#pragma unroll
            for (int c = 0; c < 4; c++) acc[a][b][c] = 0.f;

    const int arow = mh * 64 + (lane & 15);
    const int brow = nq * 32 + ((lane >> 4) << 3) + (lane & 7);

    pf_plane(sbase, 0u, gAt, tid);
    pf_plane(sbase, 16384u, Bw, tid);
    cp_commit();
    pf_plane(sbase, 32768u, gAt + 1024, tid);
    pf_plane(sbase, 49152u, Bw + 1024, tid);
    cp_commit();

    cp_wait1();
    __syncthreads();
    mma_chunk(acc, sbase, sbase + 16384u, arow, brow, lane);
    cp_wait0();
    __syncthreads();
    mma_chunk(acc, sbase + 32768u, sbase + 49152u, arow, brow, lane);
    __syncthreads();

    const size_t base = tile * 128;
    const int rr = lane >> 2, cc = (lane & 3) * 2;
    float* stage = (float*)smem;   // stride 84 floats, cols 0..79
#pragma unroll
    for (int mt = 0; mt < 4; mt++)
#pragma unroll
        for (int nt = 0; nt < 4; nt++) {
            int col = nq * 32 + nt * 8 + cc;
            if (col < 80) {
                int r = mh * 64 + mt * 16 + rr;
                stage[r * 84 + col] = acc[mt][nt][0];
                stage[r * 84 + col + 1] = acc[mt][nt][1];
                stage[(r + 8) * 84 + col] = acc[mt][nt][2];
                stage[(r + 8) * 84 + col + 1] = acc[mt][nt][3];
            }
        }
    __syncthreads();
    for (int t = tid; t < 128 * 10; t += 256) {
        int nn = t / 10, c4 = t % 10;
        size_t gn = base + nn;
        if (gn < (size_t)n)
            *(float4*)(g_s + gn * 40 + c4 * 4) = *(float4*)(stage + nn * 84 + c4 * 4);
    }
    for (int t = tid; t < 128 * 20; t += 256) {
        int nn = t / 20, j = t % 20;
        size_t gn = base + nn;
        if (gn < (size_t)n) {
            __half2 h = __floats2half2_rn(stage[nn * 84 + 40 + 2 * j],
                                          stage[nn * 84 + 41 + 2 * j]);
            g_t[gn * 24 + j] = *(unsigned*)&h;
        }
    }
}

// ---------------- final aggregation: out[v] = s[v] + mean_t + b (fp16 gather) ----------------
__global__ __launch_bounds__(256)
void k_aggf(const float* __restrict__ b, float* __restrict__ out, int n) {
    grid_wait();
    int w = (blockIdx.x * 256 + threadIdx.x) >> 5;
    int lane = threadIdx.x & 31;
    if (w >= n) return;
    int beg = g_rp[w], end = g_rp[w + 1];

    const int l = min(lane, 19);
    float2 acc = make_float2(0.f, 0.f);
    int e = beg;
    for (; e + 2 <= end; e += 2) {
        int u0 = g_col[e], u1 = g_col[e + 1];
        unsigned q0 = g_t[(size_t)u0 * 24 + l];
        unsigned q1 = g_t[(size_t)u1 * 24 + l];
        if (lane < 20) {
            float2 f0 = __half22float2(*(__half2*)&q0);
            float2 f1 = __half22float2(*(__half2*)&q1);
            acc.x += f0.x + f1.x;
            acc.y += f0.y + f1.y;
        }
    }
    if (e < end) {
        int u0 = g_col[e];
        unsigned q0 = g_t[(size_t)u0 * 24 + l];
        if (lane < 20) {
            float2 f0 = __half22float2(*(__half2*)&q0);
            acc.x += f0.x;
            acc.y += f0.y;
        }
    }
    if (lane < 20) {
        float inv = 1.0f / (float)max(end - beg, 1);
        float2 s = *(const float2*)(g_s + (size_t)w * 40 + 2 * lane);
        float2 bb = *(const float2*)(b + 2 * lane);
        float2 r;
        r.x = fmaf(acc.x, inv, s.x + bb.x);
        r.y = fmaf(acc.y, inv, s.y + bb.y);
        *(float2*)(out + (size_t)w * 40 + 2 * lane) = r;
    }
}

// ---------------- PDL launch helper ----------------
template <typename K, typename... Args>
static void launch_pdl(K kern, int grid, int block, size_t smem, Args... args) {
    cudaLaunchConfig_t cfg = {};
    cfg.gridDim = dim3(grid, 1, 1);
    cfg.blockDim = dim3(block, 1, 1);
    cfg.dynamicSmemBytes = smem;
    cfg.stream = 0;
    cudaLaunchAttribute attr[1];
    attr[0].id = cudaLaunchAttributeProgrammaticStreamSerialization;
    attr[0].val.programmaticStreamSerializationAllowed = 1;
    cfg.attrs = attr;
    cfg.numAttrs = 1;
    cudaLaunchKernelEx(&cfg, kern, args...);
}

// ---------------- launch ----------------
extern "C" void kernel_launch(void* const* d_in, const int* in_sizes, int n_in,
                              void* d_out, int out_size) {
    const float* x   = (const float*)d_in[0];
    const int*   src = (const int*)d_in[1];
    const int*   dst = (const int*)d_in[2];
    const float* ws1 = (const float*)d_in[3];
    const float* wn1 = (const float*)d_in[4];
    const float* b1  = (const float*)d_in[5];
    const float* ws2 = (const float*)d_in[6];
    const float* wn2 = (const float*)d_in[7];
    const float* b2  = (const float*)d_in[8];
    const float* ws3 = (const float*)d_in[9];
    const float* wn3 = (const float*)d_in[10];
    const float* b3  = (const float*)d_in[11];
    const float* ws4 = (const float*)d_in[12];
    const float* wn4 = (const float*)d_in[13];
    const float* b4  = (const float*)d_in[14];

    const int n = in_sizes[0] / 128;
    const int E = in_sizes[1];
    const int tiles = (n + 127) / 128;

    const int SMEM_H = 96 * 1024;
    const int SMEM_F = 64 * 1024;
    cudaFuncSetAttribute(k_gemm_hid, cudaFuncAttributeMaxDynamicSharedMemorySize, SMEM_H);
    cudaFuncSetAttribute(k_gemm_fin, cudaFuncAttributeMaxDynamicSharedMemorySize, SMEM_F);

    uint4* pB;
    int* pDeg;
    cudaGetSymbolAddress((void**)&pB, g_B);
    cudaGetSymbolAddress((void**)&pDeg, g_deg);

    // fork: CSR chain on a side stream, overlapped with preps
    cudaStream_t s2;
    cudaStreamCreateWithFlags(&s2, cudaStreamNonBlocking);
    cudaEvent_t evFork, evJoin;
    cudaEventCreateWithFlags(&evFork, cudaEventDisableTiming);
    cudaEventCreateWithFlags(&evJoin, cudaEventDisableTiming);

    cudaEventRecord(evFork, 0);
    cudaStreamWaitEvent(s2, evFork, 0);

    cudaMemsetAsync(pDeg, 0, (size_t)n * sizeof(int), s2);
    const int e4 = (E / 4 + 255) / 256;
    k_count<<<e4, 256, 0, s2>>>(dst, E);
    int nb = (n + 511) / 512;
    k_scan1<<<nb, 512, 0, s2>>>(n);
    k_scan3b<<<nb, 512, 0, s2>>>(n, E, nb);
    k_scatter<<<e4, 256, 0, s2>>>(src, dst, E);
    cudaEventRecord(evJoin, s2);

    k_prep_all<<<64 + (n * 32 + 255) / 256, 256>>>(x, ws1, wn1, ws2, wn2,
                                                   ws3, wn3, ws4, wn4, n);
    cudaStreamWaitEvent(0, evJoin, 0);

    const int ga = (n + 7) / 8;

    // L1..L3: aggm triggers; gemm (PDL) overlaps h-phase with aggm tail
    k_aggm<<<ga, 256>>>(n);
    launch_pdl(k_gemm_hid, tiles, 256, (size_t)SMEM_H, (const uint4*)(pB + 0 * 4096), b1, n);
    k_aggm<<<ga, 256>>>(n);
    launch_pdl(k_gemm_hid, tiles, 256, (size_t)SMEM_H, (const uint4*)(pB + 1 * 4096), b2, n);
    k_aggm<<<ga, 256>>>(n);
    launch_pdl(k_gemm_hid, tiles, 256, (size_t)SMEM_H, (const uint4*)(pB + 2 * 4096), b3, n);
    // L4 + final gather
    launch_pdl(k_gemm_fin, tiles, 256, (size_t)SMEM_F, (const uint4*)(pB + 3 * 4096), b4, n);
    launch_pdl(k_aggf, ga, 256, (size_t)0, (const float*)b4, (float*)d_out, n);

    cudaEventDestroy(evFork);
    cudaEventDestroy(evJoin);
    cudaStreamDestroy(s2);
}